// round 2
// baseline (speedup 1.0000x reference)
#include <cuda_runtime.h>
#include <math.h>

// Problem constants
#define Bn   8
#define CIN  320
#define COUT 320
#define Hh   64
#define Ww   64
#define KK   9      // k*k
#define HW   4096   // 64*64

// Scratch (no cudaMalloc allowed)
__device__ float g_Q[CIN * KK * KK];            // Cayley Q per Cin block [320][9][9]
__device__ float g_ft[CIN * KK * COUT];         // transformed filter, layout [c][j][o]

// ---------------------------------------------------------------------------
// Kernel A: projection + Cayley per Cin block. One thread per n.
// ---------------------------------------------------------------------------
__global__ void cayley_kernel(const float* __restrict__ R) {
    int n = blockIdx.x * blockDim.x + threadIdx.x;
    if (n >= CIN) return;

    float r[9][9];
    float ss = 0.f;
    #pragma unroll
    for (int i = 0; i < 9; i++)
        #pragma unroll
        for (int j = 0; j < 9; j++) {
            float v = R[n * 81 + i * 9 + j];
            r[i][j] = v;
            ss += v * v;
        }
    float norm = sqrtf(ss);
    const float eps = 0.081f / sqrtf(320.0f);   // EPS / sqrt(Cin)
    float sc = (norm <= eps) ? 1.0f : (eps / norm);

    // skew = 0.5*(Rp - Rp^T) = 0.5*sc*(r - r^T)
    float S[9][9];
    #pragma unroll
    for (int i = 0; i < 9; i++)
        #pragma unroll
        for (int j = 0; j < 9; j++)
            S[i][j] = 0.5f * sc * (r[i][j] - r[j][i]);

    // A = I + S ; V = I ; Gauss-Jordan with partial pivoting -> V = inv(I+S)
    float A[9][9], V[9][9];
    for (int i = 0; i < 9; i++)
        for (int j = 0; j < 9; j++) {
            A[i][j] = S[i][j] + (i == j ? 1.0f : 0.0f);
            V[i][j] = (i == j ? 1.0f : 0.0f);
        }
    for (int col = 0; col < 9; col++) {
        int p = col;
        float best = fabsf(A[col][col]);
        for (int row = col + 1; row < 9; row++) {
            float a = fabsf(A[row][col]);
            if (a > best) { best = a; p = row; }
        }
        if (p != col) {
            for (int j = 0; j < 9; j++) {
                float t = A[col][j]; A[col][j] = A[p][j]; A[p][j] = t;
                t = V[col][j]; V[col][j] = V[p][j]; V[p][j] = t;
            }
        }
        float d = 1.0f / A[col][col];
        for (int j = 0; j < 9; j++) { A[col][j] *= d; V[col][j] *= d; }
        for (int row = 0; row < 9; row++) {
            if (row == col) continue;
            float f = A[row][col];
            for (int j = 0; j < 9; j++) {
                A[row][j] -= f * A[col][j];
                V[row][j] -= f * V[col][j];
            }
        }
    }

    // Q = (I - S) @ V
    for (int i = 0; i < 9; i++)
        for (int j = 0; j < 9; j++) {
            float acc = 0.f;
            for (int k = 0; k < 9; k++) {
                float m = (i == k ? 1.0f : 0.0f) - S[i][k];
                acc += m * V[k][j];
            }
            g_Q[n * 81 + i * 9 + j] = acc;
        }
}

// ---------------------------------------------------------------------------
// Kernel B: filt_mid[n,i,m] = sum_j Q[n,i,j] * W.flat[n*2880 + j*320 + m]
// The flat filt_mid buffer IS the OIHW conv filter:
//   filt[o,c,kh,kw] = flat[o*2880 + c*9 + j]  with flat index n*2880+i*320+m
// We scatter directly into the conv-friendly transposed layout
//   g_ft[(c*9 + j)*320 + o]  (== g_ft[(i*320+m)*320 + n])
// ---------------------------------------------------------------------------
__global__ void filt_kernel(const float* __restrict__ W) {
    int n = blockIdx.x / 9;
    int i = blockIdx.x % 9;
    __shared__ float q[9];
    if (threadIdx.x < 9) q[threadIdx.x] = g_Q[n * 81 + i * 9 + threadIdx.x];
    __syncthreads();

    int m = threadIdx.x;   // 0..319
    const float* w = W + n * 2880 + m;
    float s = 0.f;
    #pragma unroll
    for (int j = 0; j < 9; j++) s += q[j] * w[j * 320];
    g_ft[(i * 320 + m) * 320 + n] = s;
}

// ---------------------------------------------------------------------------
// Kernel C: direct 3x3 conv, fp32, smem-tiled.
// Grid: (16 spatial tiles [4x4 of 16x16], 10 Cout tiles of 32, 8 batches)
// Block: 256 threads. Thread -> (co_id = t/32 owning 4 couts, lane -> row r =
// lane&15, col-block cb = (lane>>4)*8 owning 8 cols). 32 accumulators/thread.
// Cin consumed in chunks of 8 through shared memory (20 epochs total).
// ---------------------------------------------------------------------------
#define TC  32    // cout tile
#define CCH 8     // cin chunk

__global__ void __launch_bounds__(256, 2)
conv_kernel(const float* __restrict__ x, const float* __restrict__ bias,
            float* __restrict__ out) {
    __shared__ float xs[CCH][18][21];   // input halo tile (pitch 21 vs conflicts)
    __shared__ float fs[CCH][9][TC];    // filters for this cout tile

    int tile = blockIdx.x;
    int ty = tile >> 2, tx = tile & 3;
    int coBase = blockIdx.y * TC;
    int b = blockIdx.z;
    int t = threadIdx.x;
    int co_id = t >> 5;          // 0..7
    int lane  = t & 31;
    int r  = lane & 15;          // output row in tile
    int cb = (lane >> 4) << 3;   // 0 or 8

    int co0 = coBase + co_id * 4;
    float acc[4][8];
    #pragma unroll
    for (int u = 0; u < 4; u++) {
        float bv = bias[co0 + u];
        #pragma unroll
        for (int v = 0; v < 8; v++) acc[u][v] = bv;
    }

    int gy0 = ty * 16 - 1;
    int gx0 = tx * 16 - 1;
    const float* xb = x + (long)b * CIN * HW;

    for (int c0 = 0; c0 < CIN; c0 += CCH) {
        // load input halo tiles: CCH*18*18 = 2592 elements
        #pragma unroll
        for (int e = t; e < CCH * 18 * 18; e += 256) {
            int cc  = e / 324;
            int rem = e - cc * 324;
            int ry  = rem / 18;
            int rx  = rem - ry * 18;
            int gy = gy0 + ry, gx = gx0 + rx;
            float v = 0.f;
            if ((unsigned)gy < 64u && (unsigned)gx < 64u)
                v = xb[(c0 + cc) * HW + gy * 64 + gx];
            xs[cc][ry][rx] = v;
        }
        // load filters: CCH*9*32 = 2304 elements, coalesced over cout
        #pragma unroll
        for (int e = t; e < CCH * 9 * TC; e += 256) {
            int cc  = e / (9 * TC);
            int rem = e - cc * (9 * TC);
            int j   = rem / TC;
            int o   = rem - j * TC;
            fs[cc][j][o] = g_ft[((c0 + cc) * 9 + j) * 320 + coBase + o];
        }
        __syncthreads();

        #pragma unroll
        for (int cc = 0; cc < CCH; cc++) {
            #pragma unroll
            for (int kh = 0; kh < 3; kh++) {
                float xr[10];
                #pragma unroll
                for (int q = 0; q < 10; q++)
                    xr[q] = xs[cc][r + kh][cb + q];
                #pragma unroll
                for (int kw = 0; kw < 3; kw++) {
                    int j = kh * 3 + kw;
                    float f0 = fs[cc][j][co_id * 4 + 0];
                    float f1 = fs[cc][j][co_id * 4 + 1];
                    float f2 = fs[cc][j][co_id * 4 + 2];
                    float f3 = fs[cc][j][co_id * 4 + 3];
                    #pragma unroll
                    for (int v = 0; v < 8; v++) {
                        float xv = xr[v + kw];
                        acc[0][v] = fmaf(f0, xv, acc[0][v]);
                        acc[1][v] = fmaf(f1, xv, acc[1][v]);
                        acc[2][v] = fmaf(f2, xv, acc[2][v]);
                        acc[3][v] = fmaf(f3, xv, acc[3][v]);
                    }
                }
            }
        }
        __syncthreads();
    }

    // write out: 8 consecutive cols per thread -> 2 x float4 per cout
    float* ob = out + ((long)b * COUT + co0) * HW + (ty * 16 + r) * 64 + tx * 16 + cb;
    #pragma unroll
    for (int u = 0; u < 4; u++) {
        float4 a = make_float4(acc[u][0], acc[u][1], acc[u][2], acc[u][3]);
        float4 c = make_float4(acc[u][4], acc[u][5], acc[u][6], acc[u][7]);
        *(float4*)(ob + u * HW)     = a;
        *(float4*)(ob + u * HW + 4) = c;
    }
}

// ---------------------------------------------------------------------------
extern "C" void kernel_launch(void* const* d_in, const int* in_sizes, int n_in,
                              void* d_out, int out_size) {
    const float* x    = (const float*)d_in[0];   // [8,320,64,64]
    const float* R    = (const float*)d_in[1];   // [320,9,9]
    const float* W    = (const float*)d_in[2];   // [320,320,3,3]
    const float* bias = (const float*)d_in[3];   // [320]
    float* out = (float*)d_out;                  // [8,320,64,64]

    cayley_kernel<<<5, 64>>>(R);
    filt_kernel<<<CIN * 9, COUT>>>(W);
    conv_kernel<<<dim3(16, 10, 8), 256>>>(x, bias, out);
}

// round 4
// speedup vs baseline: 1.5201x; 1.5201x over previous
#include <cuda_runtime.h>
#include <cuda_bf16.h>
#include <math.h>

// Problem constants
#define Bn   8
#define CIN  320
#define COUT 320
#define HW   4096
#define NCH  20      // cin chunks of 16
#define CC   16      // channels per chunk

// ---------------------------------------------------------------------------
// Device scratch (no cudaMalloc allowed)
// ---------------------------------------------------------------------------
__device__ float g_Q[CIN * 81];

// Padded, channel-chunked, split-bf16 input: [b][cch][y 0..65][x 0..65][c16]
#define XG_ELEMS (8u * 20u * 66u * 66u * 16u)   // 11,151,360
__device__ __align__(16) __nv_bfloat16 g_xh[XG_ELEMS];
__device__ __align__(16) __nv_bfloat16 g_xl[XG_ELEMS];

// Split-bf16 transformed filter: [cch][j][cout][c16]
#define FG_ELEMS (20u * 9u * 320u * 16u)        // 921,600
__device__ __align__(16) __nv_bfloat16 g_fh[FG_ELEMS];
__device__ __align__(16) __nv_bfloat16 g_fl[FG_ELEMS];

// ---------------------------------------------------------------------------
// Kernel A: projection + Cayley per Cin block. One thread per n.
// ---------------------------------------------------------------------------
__global__ void cayley_kernel(const float* __restrict__ R) {
    int n = blockIdx.x * blockDim.x + threadIdx.x;
    if (n >= CIN) return;

    float r[9][9];
    float ss = 0.f;
    #pragma unroll
    for (int i = 0; i < 9; i++)
        #pragma unroll
        for (int j = 0; j < 9; j++) {
            float v = R[n * 81 + i * 9 + j];
            r[i][j] = v;
            ss += v * v;
        }
    float norm = sqrtf(ss);
    const float eps = 0.081f / sqrtf(320.0f);   // EPS / sqrt(Cin)
    float sc = (norm <= eps) ? 1.0f : (eps / norm);

    float S[9][9];
    #pragma unroll
    for (int i = 0; i < 9; i++)
        #pragma unroll
        for (int j = 0; j < 9; j++)
            S[i][j] = 0.5f * sc * (r[i][j] - r[j][i]);

    float A[9][9], V[9][9];
    for (int i = 0; i < 9; i++)
        for (int j = 0; j < 9; j++) {
            A[i][j] = S[i][j] + (i == j ? 1.0f : 0.0f);
            V[i][j] = (i == j ? 1.0f : 0.0f);
        }
    for (int col = 0; col < 9; col++) {
        int p = col;
        float best = fabsf(A[col][col]);
        for (int row = col + 1; row < 9; row++) {
            float a = fabsf(A[row][col]);
            if (a > best) { best = a; p = row; }
        }
        if (p != col) {
            for (int j = 0; j < 9; j++) {
                float tq = A[col][j]; A[col][j] = A[p][j]; A[p][j] = tq;
                tq = V[col][j]; V[col][j] = V[p][j]; V[p][j] = tq;
            }
        }
        float d = 1.0f / A[col][col];
        for (int j = 0; j < 9; j++) { A[col][j] *= d; V[col][j] *= d; }
        for (int row = 0; row < 9; row++) {
            if (row == col) continue;
            float f = A[row][col];
            for (int j = 0; j < 9; j++) {
                A[row][j] -= f * A[col][j];
                V[row][j] -= f * V[col][j];
            }
        }
    }

    for (int i = 0; i < 9; i++)
        for (int j = 0; j < 9; j++) {
            float acc = 0.f;
            for (int k = 0; k < 9; k++) {
                float m = (i == k ? 1.0f : 0.0f) - S[i][k];
                acc += m * V[k][j];
            }
            g_Q[n * 81 + i * 9 + j] = acc;
        }
}

// ---------------------------------------------------------------------------
// Kernel B: filter transform + split into hi/lo bf16.
// filt_mid[n,i,m] flat index == OIHW filter flat index:
//   o = n, c = (i*320+m)/9, j = (i*320+m)%9   (validated by round-2 pass)
// Output layout: g_fh/g_fl[((cch*9 + j)*320 + o)*16 + cw], c = cch*16+cw
// ---------------------------------------------------------------------------
__global__ void filt_kernel(const float* __restrict__ W) {
    int n = blockIdx.x / 9;     // Q block index == final cout o
    int i = blockIdx.x % 9;
    __shared__ float q[9];
    if (threadIdx.x < 9) q[threadIdx.x] = g_Q[n * 81 + i * 9 + threadIdx.x];
    __syncthreads();

    int m = threadIdx.x;        // 0..319
    const float* w = W + n * 2880 + m;
    float s = 0.f;
    #pragma unroll
    for (int j = 0; j < 9; j++) s += q[j] * w[j * 320];

    int lin = i * 320 + m;
    int c = lin / 9;
    int j = lin - c * 9;
    __nv_bfloat16 h = __float2bfloat16(s);
    __nv_bfloat16 l = __float2bfloat16(s - __bfloat162float(h));
    size_t di = (((size_t)(c >> 4) * 9 + j) * 320 + n) * 16 + (c & 15);
    g_fh[di] = h;
    g_fl[di] = l;
}

// ---------------------------------------------------------------------------
// Kernel Z: zero the padded x buffers (borders must be 0; interior overwritten)
// ---------------------------------------------------------------------------
__global__ void zero_x_kernel() {
    unsigned e = blockIdx.x * 256u + threadIdx.x;
    unsigned n16 = XG_ELEMS / 8u;   // uint4 count
    if (e < n16) {
        uint4 z = make_uint4(0, 0, 0, 0);
        ((uint4*)g_xh)[e] = z;
        ((uint4*)g_xl)[e] = z;
    }
}

// ---------------------------------------------------------------------------
// Kernel X: NCHW fp32 -> padded [b][cch][y+1][x+1][c16] split bf16.
// One block per (b, cch, y): transposes 16 channels x 64 cols via smem.
// ---------------------------------------------------------------------------
__global__ void __launch_bounds__(256) xsplit_kernel(const float* __restrict__ x) {
    int blk = blockIdx.x;
    int y = blk & 63;
    int cch = (blk >> 6) % NCH;
    int b = blk / (64 * NCH);
    int t = threadIdx.x;

    __shared__ float tile[16][65];
    #pragma unroll
    for (int pass = 0; pass < 4; pass++) {
        int cw = pass * 4 + (t >> 6);
        int xc = t & 63;
        tile[cw][xc] = x[(((size_t)b * 320 + cch * 16 + cw) * 64 + y) * 64 + xc];
    }
    __syncthreads();

    size_t dst = ((((size_t)b * NCH + cch) * 66 + (y + 1)) * 66 + 1) * 16;
    #pragma unroll
    for (int e = 0; e < 4; e++) {
        int idx = e * 256 + t;          // 0..1023
        int xc = idx >> 4;
        int cw = idx & 15;
        float v = tile[cw][xc];
        __nv_bfloat16 h = __float2bfloat16(v);
        __nv_bfloat16 l = __float2bfloat16(v - __bfloat162float(h));
        g_xh[dst + (size_t)xc * 16 + cw] = h;
        g_xl[dst + (size_t)xc * 16 + cw] = l;
    }
}

// ---------------------------------------------------------------------------
// MMA helpers
// ---------------------------------------------------------------------------
__device__ __forceinline__ unsigned smem_u32(const void* p) {
    return (unsigned)__cvta_generic_to_shared(p);
}

__device__ __forceinline__ void ldm_x4(unsigned r[4], unsigned addr) {
    asm volatile("ldmatrix.sync.aligned.m8n8.x4.shared.b16 {%0,%1,%2,%3}, [%4];"
                 : "=r"(r[0]), "=r"(r[1]), "=r"(r[2]), "=r"(r[3]) : "r"(addr));
}
__device__ __forceinline__ void ldm_x2(unsigned r[2], unsigned addr) {
    asm volatile("ldmatrix.sync.aligned.m8n8.x2.shared.b16 {%0,%1}, [%2];"
                 : "=r"(r[0]), "=r"(r[1]) : "r"(addr));
}
__device__ __forceinline__ void mma_bf16(float c[4], const unsigned a[4], const unsigned b[2]) {
    asm volatile(
        "mma.sync.aligned.m16n8k16.row.col.f32.bf16.bf16.f32 "
        "{%0,%1,%2,%3}, {%4,%5,%6,%7}, {%8,%9}, {%0,%1,%2,%3};"
        : "+f"(c[0]), "+f"(c[1]), "+f"(c[2]), "+f"(c[3])
        : "r"(a[0]), "r"(a[1]), "r"(a[2]), "r"(a[3]), "r"(b[0]), "r"(b[1]));
}

// ---------------------------------------------------------------------------
// Kernel C: implicit-GEMM conv via mma.sync bf16 (split hi/lo, 3 terms).
// CTA: 128 pixels (2 image rows x 64) x 32 couts. 8 warps, each 16 pix x 32 co.
// K loop: 20 chunks of 16 channels; inner loop over the 9 spatial shifts.
// ---------------------------------------------------------------------------
#define XS_ELEMS (4 * 66 * 16)      // 4224 bf16 per term
#define BS_ELEMS (9 * 32 * 16)      // 4608 bf16 per term

__global__ void __launch_bounds__(256) conv_mma_kernel(
    const float* __restrict__ bias, float* __restrict__ out)
{
    __shared__ __align__(16) char pool[(XS_ELEMS * 2 + BS_ELEMS * 2) * 2];
    __nv_bfloat16* xsH = (__nv_bfloat16*)pool;
    __nv_bfloat16* xsL = xsH + XS_ELEMS;
    __nv_bfloat16* bsH = xsL + XS_ELEMS;
    __nv_bfloat16* bsL = bsH + BS_ELEMS;
    float* ds = (float*)pool;                 // epilogue reuse: 128*33 f32

    int tileY = blockIdx.x;                   // 0..31
    int o0 = blockIdx.y * 32;                 // cout tile base
    int b = blockIdx.z;
    int t = threadIdx.x;
    int warp = t >> 5, lane = t & 31;
    int iy0 = tileY * 2;

    float acc[4][4];
    #pragma unroll
    for (int nt = 0; nt < 4; nt++)
        #pragma unroll
        for (int u = 0; u < 4; u++) acc[nt][u] = 0.f;

    unsigned xsHu = smem_u32(xsH);
    unsigned xsLu = smem_u32(xsL);
    unsigned bsHu = smem_u32(bsH);
    unsigned bsLu = smem_u32(bsL);

    // ldmatrix A per-lane address components (m16k16 as 4 8x8 mats)
    int arow = lane & 15;                 // row within m16 tile
    int p = warp * 16 + arow;             // pixel 0..127
    int aiy = p >> 6, aix = p & 63;
    unsigned akh = (unsigned)(lane >> 4) * 16u;   // k-half byte offset

    // ldmatrix B per-lane address components (two 8x8 mats per n8 tile)
    int bn = lane & 7;
    unsigned bkh = (unsigned)((lane >> 3) & 1) * 16u;

    for (int cch = 0; cch < NCH; cch++) {
        // --- load x tiles (contiguous 8448B each) ---
        {
            size_t base = ((((size_t)b * NCH + cch) * 66 + iy0) * 66) * 16;
            const uint4* sH = (const uint4*)(g_xh + base);
            const uint4* sL = (const uint4*)(g_xl + base);
            uint4* dH = (uint4*)xsH;
            uint4* dL = (uint4*)xsL;
            #pragma unroll
            for (int e = 0; e < 3; e++) {
                int idx = e * 256 + t;
                if (idx < 528) { dH[idx] = sH[idx]; dL[idx] = sL[idx]; }
            }
        }
        // --- load filter tiles: 9 j-blocks of 512 elems each ---
        {
            uint4* dH = (uint4*)bsH;
            uint4* dL = (uint4*)bsL;
            #pragma unroll
            for (int e = 0; e < 3; e++) {
                int idx = e * 256 + t;                 // 0..575
                if (idx < 576) {
                    int j = idx >> 6, u = idx & 63;
                    size_t s = ((((size_t)cch * 9 + j) * 320 + o0) * 16) >> 3;
                    dH[idx] = ((const uint4*)g_fh)[s + u];
                    dL[idx] = ((const uint4*)g_fl)[s + u];
                }
            }
        }
        __syncthreads();

        #pragma unroll
        for (int j = 0; j < 9; j++) {
            const int dy = j / 3, dx = j % 3;
            unsigned aoff = (unsigned)(((aiy + dy) * 66 + (aix + dx)) * 32) + akh;
            unsigned aH[4], aL[4];
            ldm_x4(aH, xsHu + aoff);
            ldm_x4(aL, xsLu + aoff);
            #pragma unroll
            for (int nt = 0; nt < 4; nt++) {
                unsigned boff = (unsigned)((j * 32 + nt * 8 + bn) * 32) + bkh;
                unsigned bH[2], bL[2];
                ldm_x2(bH, bsHu + boff);
                ldm_x2(bL, bsLu + boff);
                mma_bf16(acc[nt], aH, bH);   // xh*fh
                mma_bf16(acc[nt], aH, bL);   // xh*fl
                mma_bf16(acc[nt], aL, bH);   // xl*fh
            }
        }
        __syncthreads();
    }

    // --- epilogue: transpose through smem for coalesced NCHW stores ---
    {
        int r = lane >> 2;
        int cp = (lane & 3) * 2;
        #pragma unroll
        for (int nt = 0; nt < 4; nt++) {
            int col = nt * 8 + cp;
            ds[(warp * 16 + r) * 33 + col]     = acc[nt][0];
            ds[(warp * 16 + r) * 33 + col + 1] = acc[nt][1];
            ds[(warp * 16 + r + 8) * 33 + col]     = acc[nt][2];
            ds[(warp * 16 + r + 8) * 33 + col + 1] = acc[nt][3];
        }
    }
    __syncthreads();
    #pragma unroll
    for (int e = 0; e < 16; e++) {
        int idx = e * 256 + t;                // 0..4095
        int p2 = idx & 127;
        int col = idx >> 7;                   // 0..31
        float v = ds[p2 * 33 + col] + bias[o0 + col];
        out[(((size_t)b * COUT + o0 + col) * 64 + iy0 + (p2 >> 6)) * 64 + (p2 & 63)] = v;
    }
}

// ---------------------------------------------------------------------------
extern "C" void kernel_launch(void* const* d_in, const int* in_sizes, int n_in,
                              void* d_out, int out_size) {
    const float* x    = (const float*)d_in[0];   // [8,320,64,64]
    const float* R    = (const float*)d_in[1];   // [320,9,9]
    const float* W    = (const float*)d_in[2];   // [320,320,3,3]
    const float* bias = (const float*)d_in[3];   // [320]
    float* out = (float*)d_out;                  // [8,320,64,64]

    cayley_kernel<<<5, 64>>>(R);
    filt_kernel<<<CIN * 9, COUT>>>(W);
    zero_x_kernel<<<(XG_ELEMS / 8 + 255) / 256, 256>>>();
    xsplit_kernel<<<Bn * NCH * 64, 256>>>(x);
    conv_mma_kernel<<<dim3(32, 10, 8), 256>>>(bias, out);
}